// round 12
// baseline (speedup 1.0000x reference)
#include <cuda_runtime.h>
#include <cuda_bf16.h>
#include <math_constants.h>
#include <cstdint>

// VQ-VAE vector quantizer via warp-level bf16 mma.sync (sm_80 baseline ISA,
// compiles at the harness's sm_103 PTX target) + exact fp32 tie resolution.
// Frozen reference pipeline (must match bitwise):
//   d_k = fl32( fl32(A - 2*M_k) + B_k ),  A = x^2 float2-leaf tree,
//   M_k = ascending-d fp32 FMA chain,  B_k = ascending chain,
//   argmin tie -> lowest index.
// Approx phase: M~ = Ah.Bh + Ah.Bl + Al.Bh (bf16 splits, f32 acc).
//   |dist~ - dist_exact| <= delta ~ 1.4e-5; EPS = 3e-4 >> 2*delta.
//   Track true top-3 approx dists per position. If b3 > b1+EPS the exact
//   argmin is provably in {i1,i2} -> recompute those 2 with the frozen
//   chain. Else full exact scan (rare).
// R12 fix: B fragments via NON-transposed ldmatrix (smem B image is
// [n][k] row-major; .trans scrambled every MMA in R11).

#define ENC_OFF   4194304
#define LOSS_OFF  4259840
#define NLL_OFF   4259841
#define TOTAL_OUT 4259842
#define NTILES    512
#define EPS       3.0e-4f
#define BROW      72        // bf16 elems per image row (144 B, LDSM conflict-free)

// smem offsets (bytes)
#define SM_XS    0          // fp32 X tile [64][128]        32768
#define SM_AH    32768      // A-hi bf16 [128][72]          18432
#define SM_AL    51200      // A-lo bf16 [128][72]          18432
#define SM_BB    69632      // B bufs: (Bh|Bl) x2           36864
#define SM_EBS   106496     // fp32 ||e||^2 [1024]           4096
#define SM_AS    110592     // fp32 A [128]                   512
#define SM_IDX   111104     // winners [128]                  512
#define SM_WSUM  111616
#define SM_CNT   111680
#define SM_LIST  111696     // fallback list [128]            512
#define SM_TOTAL 112256
// candidate arrays overlay SM_BB after the MMA phase:
#define CB1 (SM_BB)
#define CB2 (SM_BB + 512)
#define CB3 (SM_BB + 1024)
#define CI1 (SM_BB + 1536)
#define CI2 (SM_BB + 2048)

typedef unsigned long long ull;
typedef unsigned int u32;

__device__ double g_loss_acc;                 // self-reset
__device__ int    g_fin;                      // self-reset
__device__ __align__(16) float g_eB[1024];    // exact ||e||^2 chains
__device__ __align__(16) __nv_bfloat16 g_Bh[1024 * BROW];  // hi image (padded rows)
__device__ __align__(16) __nv_bfloat16 g_Bl[1024 * BROW];  // lo image

__device__ __forceinline__ void cp16(u32 dst, const void* src) {
    asm volatile("cp.async.cg.shared.global [%0], [%1], 16;"
                 :: "r"(dst), "l"(src) : "memory");
}
#define CP_COMMIT() asm volatile("cp.async.commit_group;" ::: "memory")
#define CP_WAIT0()  asm volatile("cp.async.wait_group 0;" ::: "memory")
#define CP_WAIT1()  asm volatile("cp.async.wait_group 1;" ::: "memory")

#define LDSM_X4(r, a)                                                        \
    asm volatile("ldmatrix.sync.aligned.m8n8.x4.shared.b16 {%0,%1,%2,%3}, [%4];" \
        : "=r"((r)[0]), "=r"((r)[1]), "=r"((r)[2]), "=r"((r)[3]) : "r"(a))
#define LDSM_X2(r0, r1, a)                                                   \
    asm volatile("ldmatrix.sync.aligned.m8n8.x2.shared.b16 {%0,%1}, [%2];"   \
        : "=r"(r0), "=r"(r1) : "r"(a))
#define MMA_BF16(c, a, b0, b1)                                               \
    asm volatile("mma.sync.aligned.m16n8k16.row.col.f32.bf16.bf16.f32 "      \
        "{%0,%1,%2,%3}, {%4,%5,%6,%7}, {%8,%9}, {%0,%1,%2,%3};"              \
        : "+f"((c)[0]), "+f"((c)[1]), "+f"((c)[2]), "+f"((c)[3])             \
        : "r"((a)[0]), "r"((a)[1]), "r"((a)[2]), "r"((a)[3]), "r"(b0), "r"(b1))

// top-3 insert, strict < (ascending scan order => lowest index kept on ties)
__device__ __forceinline__ void t3u(float& b1, float& b2, float& b3,
                                    int& i1, int& i2, float v, int k) {
    if (v < b3) {
        if (v < b2) {
            b3 = b2;
            if (v < b1) { b2 = b1; i2 = i1; b1 = v; i1 = k; }
            else        { b2 = v; i2 = k; }
        } else b3 = v;
    }
}
// lexicographic (value, index) insert for cross-lane merges
__device__ __forceinline__ void t3x(float& b1, float& b2, float& b3,
                                    int& i1, int& i2, float v, int k) {
    if (v < b1 || (v == b1 && k < i1)) { b3 = b2; b2 = b1; i2 = i1; b1 = v; i1 = k; }
    else if (v < b2 || (v == b2 && k < i2)) { b3 = b2; b2 = v; i2 = k; }
    else if (v < b3) b3 = v;
}

// Kernel 0: bf16 hi/lo codebook images (padded rows) + exact ||e||^2 chains.
__global__ void __launch_bounds__(256) vq_prep(const float* __restrict__ emb) {
    int t = blockIdx.x * blockDim.x + threadIdx.x;   // 65536
    int k = t >> 6, d = t & 63;
    float e = emb[t];
    __nv_bfloat16 hh = __float2bfloat16(e);
    __nv_bfloat16 ll = __float2bfloat16(__fadd_rn(e, -__bfloat162float(hh)));
    g_Bh[k * BROW + d] = hh;
    g_Bl[k * BROW + d] = ll;
    if (t < 1024) {
        const float* row = emb + (size_t)t * 64;
        float b = 0.0f;
        #pragma unroll
        for (int i = 0; i < 64; i++) b = __fmaf_rn(row[i], row[i], b);
        g_eB[t] = b;
    }
}

__global__ void __launch_bounds__(256, 2)
vq_main(const float* __restrict__ x, const float* __restrict__ emb,
        float* __restrict__ out, int out_size) {
    extern __shared__ __align__(1024) unsigned char sm[];
    float* Xs   = (float*)(sm + SM_XS);
    float* eBs  = (float*)(sm + SM_EBS);
    float* As   = (float*)(sm + SM_AS);
    int*   idxs = (int*)(sm + SM_IDX);
    float* wsum = (float*)(sm + SM_WSUM);
    int*   scnt = (int*)(sm + SM_CNT);
    int*   slist = (int*)(sm + SM_LIST);

    const u32 base = (u32)__cvta_generic_to_shared(sm);
    const int tid = threadIdx.x;
    const int wid = tid >> 5, lane = tid & 31;
    const int b  = blockIdx.x >> 3;
    const int p0 = (blockIdx.x & 7) * 128;
    const int m0 = wid * 16;

    if (tid == 0) *scnt = 0;

    // ---- prologue: group0 = X + eB, group1 = B chunk 0 ----
    {
        const float* xb = x + (size_t)b * 65536 + p0;
        #pragma unroll
        for (int i = 0; i < 8; i++) {
            int c = tid + i * 256;           // 2048 16B-chunks
            int d = c >> 5, po = c & 31;
            cp16(base + SM_XS + d * 512 + po * 16, xb + d * 1024 + po * 4);
        }
        cp16(base + SM_EBS + tid * 16, (const char*)g_eB + tid * 16);
        CP_COMMIT();
        #pragma unroll
        for (int i = 0; i < 5; i++) {        // 1152 chunks (Bh 576 + Bl 576)
            int c = tid + i * 256;
            if (c < 1152) {
                int sp = c >= 576;
                int cc = c - sp * 576;
                const char* src = (const char*)(sp ? g_Bl : g_Bh) + cc * 16;
                cp16(base + SM_BB + sp * 9216 + cc * 16, src);
            }
        }
        CP_COMMIT();
        CP_WAIT1();     // X + eB landed (B0 may still fly)
    }
    __syncthreads();

    // ---- build Ah/Al bf16 images (row = position, 144B stride) ----
    if (tid < 128) {
        #pragma unroll
        for (int d2 = 0; d2 < 32; d2++) {
            float v0 = Xs[(2 * d2) * 128 + tid];
            float v1 = Xs[(2 * d2 + 1) * 128 + tid];
            __nv_bfloat16 h0 = __float2bfloat16(v0), h1 = __float2bfloat16(v1);
            __nv_bfloat16 l0 = __float2bfloat16(__fadd_rn(v0, -__bfloat162float(h0)));
            __nv_bfloat16 l1 = __float2bfloat16(__fadd_rn(v1, -__bfloat162float(h1)));
            u32 hw = (u32)*(unsigned short*)&h0 | ((u32)*(unsigned short*)&h1 << 16);
            u32 lw = (u32)*(unsigned short*)&l0 | ((u32)*(unsigned short*)&l1 << 16);
            *(u32*)(sm + SM_AH + tid * 144 + d2 * 4) = hw;
            *(u32*)(sm + SM_AL + tid * 144 + d2 * 4) = lw;
        }
        // A_p exact: float2 leaves + binary tree (frozen order)
        float l[32];
        #pragma unroll
        for (int t = 0; t < 32; t++) {
            float a = Xs[(2 * t) * 128 + tid];
            float c = Xs[(2 * t + 1) * 128 + tid];
            l[t] = __fmaf_rn(c, c, __fmul_rn(a, a));
        }
        #pragma unroll
        for (int off = 16; off >= 1; off >>= 1)
            #pragma unroll
            for (int t = 0; t < 16; t++)
                if (t < off) l[t] = __fadd_rn(l[t], l[t + off]);
        As[tid] = l[0];
    }
    __syncthreads();

    // per-lane fragment addresses
    const int g = lane >> 2, tq = lane & 3;
    const int lr = (lane & 7) + ((lane >> 3) & 1) * 8;
    const u32 a_base  = base + SM_AH + (u32)((m0 + lr) * 144 + ((lane >> 4) & 1) * 16);
    const u32 al_base = a_base + (SM_AL - SM_AH);
    const int bl_ = lane & 15;
    const u32 b_off = (u32)((bl_ & 7) * 144 + ((bl_ >> 3) & 1) * 16);
    const float Ag  = As[m0 + g];
    const float Ag8 = As[m0 + 8 + g];

    // per-lane top-3 state for rows m0+g and m0+8+g
    float r0b1 = CUDART_INF_F, r0b2 = CUDART_INF_F, r0b3 = CUDART_INF_F;
    float r1b1 = CUDART_INF_F, r1b2 = CUDART_INF_F, r1b3 = CUDART_INF_F;
    int r0i1 = 0, r0i2 = 0, r1i1 = 0, r1i2 = 0;

    // ---- 16 chunks of 64 codes ----
    #pragma unroll 1
    for (int n = 0; n < 16; n++) {
        CP_WAIT0();
        __syncthreads();                 // B(n) visible; buf (n+1)&1 free

        if (n < 15) {                    // stage next chunk during compute
            const char* sbh = (const char*)g_Bh + (n + 1) * 9216;
            const char* sbl = (const char*)g_Bl + (n + 1) * 9216;
            u32 dst = base + SM_BB + (u32)(((n + 1) & 1) * 18432);
            #pragma unroll
            for (int i = 0; i < 5; i++) {
                int c = tid + i * 256;
                if (c < 1152) {
                    int sp = c >= 576;
                    int cc = c - sp * 576;
                    cp16(dst + sp * 9216 + cc * 16,
                         (sp ? sbl : sbh) + cc * 16);
                }
            }
            CP_COMMIT();
        }

        const u32 bb = base + SM_BB + (u32)((n & 1) * 18432);
        float c[8][4];
        #pragma unroll
        for (int nt = 0; nt < 8; nt++)
            #pragma unroll
            for (int q = 0; q < 4; q++) c[nt][q] = 0.0f;

        #pragma unroll
        for (int ks = 0; ks < 4; ks++) {
            u32 ah[4], al4[4];
            LDSM_X4(ah, a_base + ks * 32);
            LDSM_X4(al4, al_base + ks * 32);
            #pragma unroll
            for (int nt = 0; nt < 8; nt++) {
                u32 bh0, bh1, bl0, bl1;
                u32 ba = bb + (u32)(nt * 1152 + ks * 32) + b_off;
                LDSM_X2(bh0, bh1, ba);
                LDSM_X2(bl0, bl1, ba + 9216);
                MMA_BF16(c[nt], ah, bh0, bh1);
                MMA_BF16(c[nt], ah, bl0, bl1);
                MMA_BF16(c[nt], al4, bh0, bh1);
            }
        }

        // fold: dk = fl(fma(-2, M~, A)) + B, ascending col order
        const int n0 = n * 64;
        #pragma unroll
        for (int nt = 0; nt < 8; nt++) {
            int col = n0 + nt * 8 + 2 * tq;
            float2 eb2 = *(const float2*)&eBs[col];
            float d0 = __fadd_rn(__fmaf_rn(-2.0f, c[nt][0], Ag),  eb2.x);
            float d1 = __fadd_rn(__fmaf_rn(-2.0f, c[nt][1], Ag),  eb2.y);
            float d2 = __fadd_rn(__fmaf_rn(-2.0f, c[nt][2], Ag8), eb2.x);
            float d3 = __fadd_rn(__fmaf_rn(-2.0f, c[nt][3], Ag8), eb2.y);
            t3u(r0b1, r0b2, r0b3, r0i1, r0i2, d0, col);
            t3u(r0b1, r0b2, r0b3, r0i1, r0i2, d1, col + 1);
            t3u(r1b1, r1b2, r1b3, r1i1, r1i2, d2, col);
            t3u(r1b1, r1b2, r1b3, r1i1, r1i2, d3, col + 1);
        }
    }
    __syncthreads();    // all warps done reading B bufs before overlay

    // ---- cross-lane merge within column quads (xor 1, xor 2) ----
    #pragma unroll
    for (int s = 1; s <= 2; s <<= 1) {
        float ob1 = __shfl_xor_sync(0xffffffffu, r0b1, s);
        float ob2 = __shfl_xor_sync(0xffffffffu, r0b2, s);
        float ob3 = __shfl_xor_sync(0xffffffffu, r0b3, s);
        int   oi1 = __shfl_xor_sync(0xffffffffu, r0i1, s);
        int   oi2 = __shfl_xor_sync(0xffffffffu, r0i2, s);
        t3x(r0b1, r0b2, r0b3, r0i1, r0i2, ob1, oi1);
        t3x(r0b1, r0b2, r0b3, r0i1, r0i2, ob2, oi2);
        if (ob3 < r0b3) r0b3 = ob3;
        ob1 = __shfl_xor_sync(0xffffffffu, r1b1, s);
        ob2 = __shfl_xor_sync(0xffffffffu, r1b2, s);
        ob3 = __shfl_xor_sync(0xffffffffu, r1b3, s);
        oi1 = __shfl_xor_sync(0xffffffffu, r1i1, s);
        oi2 = __shfl_xor_sync(0xffffffffu, r1i2, s);
        t3x(r1b1, r1b2, r1b3, r1i1, r1i2, ob1, oi1);
        t3x(r1b1, r1b2, r1b3, r1i1, r1i2, ob2, oi2);
        if (ob3 < r1b3) r1b3 = ob3;
    }
    if (tq == 0) {
        int p = m0 + g;
        *(float*)(sm + CB1 + p * 4) = r0b1;
        *(float*)(sm + CB2 + p * 4) = r0b2;
        *(float*)(sm + CB3 + p * 4) = r0b3;
        *(int*)(sm + CI1 + p * 4) = r0i1;
        *(int*)(sm + CI2 + p * 4) = r0i2;
        p = m0 + 8 + g;
        *(float*)(sm + CB1 + p * 4) = r1b1;
        *(float*)(sm + CB2 + p * 4) = r1b2;
        *(float*)(sm + CB3 + p * 4) = r1b3;
        *(int*)(sm + CI1 + p * 4) = r1i1;
        *(int*)(sm + CI2 + p * 4) = r1i2;
    }
    __syncthreads();

    // ---- resolve winners (exact, frozen chains) ----
    if (tid < 128) {
        float b1 = *(float*)(sm + CB1 + tid * 4);
        float b2 = *(float*)(sm + CB2 + tid * 4);
        float b3 = *(float*)(sm + CB3 + tid * 4);
        int   i1 = *(int*)(sm + CI1 + tid * 4);
        int   i2 = *(int*)(sm + CI2 + tid * 4);
        float thr = __fadd_rn(b1, EPS);
        if (b3 > thr) {
            int w = i1;
            if (b2 <= thr) {
                float Ap = As[tid];
                const float* e1 = emb + (size_t)i1 * 64;
                const float* e2 = emb + (size_t)i2 * 64;
                float M1 = 0.0f, M2 = 0.0f;
                #pragma unroll 4
                for (int gg = 0; gg < 16; gg++) {
                    float4 a4 = *(const float4*)(e1 + gg * 4);
                    float4 c4 = *(const float4*)(e2 + gg * 4);
                    float xv0 = Xs[(gg * 4 + 0) * 128 + tid];
                    float xv1 = Xs[(gg * 4 + 1) * 128 + tid];
                    float xv2 = Xs[(gg * 4 + 2) * 128 + tid];
                    float xv3 = Xs[(gg * 4 + 3) * 128 + tid];
                    M1 = __fmaf_rn(xv0, a4.x, M1); M2 = __fmaf_rn(xv0, c4.x, M2);
                    M1 = __fmaf_rn(xv1, a4.y, M1); M2 = __fmaf_rn(xv1, c4.y, M2);
                    M1 = __fmaf_rn(xv2, a4.z, M1); M2 = __fmaf_rn(xv2, c4.z, M2);
                    M1 = __fmaf_rn(xv3, a4.w, M1); M2 = __fmaf_rn(xv3, c4.w, M2);
                }
                float d1 = __fadd_rn(__fmaf_rn(-2.0f, M1, Ap), eBs[i1]);
                float d2 = __fadd_rn(__fmaf_rn(-2.0f, M2, Ap), eBs[i2]);
                if (d2 < d1 || (d2 == d1 && i2 < i1)) w = i2;
            }
            idxs[tid] = w;
        } else {
            int o = atomicAdd(scnt, 1);
            slist[o] = tid;
        }
    }
    __syncthreads();

    // rare full exact scan, warp-cooperative
    int cnt = *scnt;
    for (int t = wid; t < cnt; t += 8) {
        int pos = slist[t];
        float Ap2 = As[pos];
        float bd = CUDART_INF_F;
        int bi = 0;
        for (int k = lane; k < 1024; k += 32) {
            const float* er = emb + (size_t)k * 64;
            float M = 0.0f;
            #pragma unroll 4
            for (int gg = 0; gg < 16; gg++) {
                float4 e4 = *(const float4*)(er + gg * 4);
                M = __fmaf_rn(Xs[(gg * 4 + 0) * 128 + pos], e4.x, M);
                M = __fmaf_rn(Xs[(gg * 4 + 1) * 128 + pos], e4.y, M);
                M = __fmaf_rn(Xs[(gg * 4 + 2) * 128 + pos], e4.z, M);
                M = __fmaf_rn(Xs[(gg * 4 + 3) * 128 + pos], e4.w, M);
            }
            float dk = __fadd_rn(__fmaf_rn(-2.0f, M, Ap2), eBs[k]);
            if (dk < bd) { bd = dk; bi = k; }
        }
        #pragma unroll
        for (int off = 16; off > 0; off >>= 1) {
            float od = __shfl_down_sync(0xffffffffu, bd, off);
            int   oi = __shfl_down_sync(0xffffffffu, bi, off);
            if (od < bd || (od == bd && oi < bi)) { bd = od; bi = oi; }
        }
        if (lane == 0) idxs[pos] = bi;
    }
    __syncthreads();

    if (tid < 128 && out_size >= TOTAL_OUT)
        out[ENC_OFF + b * 1024 + p0 + tid] = (float)idxs[tid];

    // ---- straight-through output + loss partial ----
    float lsum = 0.0f;
    #pragma unroll
    for (int j = 0; j < 32; j++) {
        int i  = tid + j * 256;
        int pp = i & 127;
        int d  = i >> 7;
        float q  = emb[(size_t)idxs[pp] * 64 + d];
        float xv = Xs[d * 128 + pp];
        float df = __fadd_rn(q, -xv);
        lsum += df * df;
        out[((size_t)b * 64 + d) * 1024 + p0 + pp] = __fadd_rn(xv, df);
    }
    #pragma unroll
    for (int off = 16; off > 0; off >>= 1)
        lsum += __shfl_down_sync(0xffffffffu, lsum, off);
    if (lane == 0) wsum[wid] = lsum;
    __syncthreads();
    if (tid == 0) {
        float t = 0.0f;
        #pragma unroll
        for (int w = 0; w < 8; w++) t += wsum[w];
        atomicAdd(&g_loss_acc, (double)t);
        __threadfence();
        int old = atomicAdd(&g_fin, 1);
        if (old == NTILES - 1) {
            if (out_size >= TOTAL_OUT) {
                float m = (float)(g_loss_acc * (1.0 / 4194304.0));
                out[LOSS_OFF] = __fadd_rn(m, __fmul_rn(0.25f, m));
                out[NLL_OFF]  = 1.0f;
            }
            g_loss_acc = 0.0;       // self-reset for next replay
            g_fin = 0;
        }
    }
}

extern "C" void kernel_launch(void* const* d_in, const int* in_sizes, int n_in,
                              void* d_out, int out_size) {
    const float* x   = (const float*)d_in[0];
    const float* emb = (const float*)d_in[1];
    if (n_in >= 2 && in_sizes[0] == 1024 * 64) {
        const float* t = x; x = emb; emb = t;
    }
    float* out = (float*)d_out;

    cudaFuncSetAttribute(vq_main, cudaFuncAttributeMaxDynamicSharedMemorySize,
                         SM_TOTAL);

    vq_prep<<<256, 256>>>(emb);
    vq_main<<<NTILES, 256, SM_TOTAL>>>(x, emb, out, out_size);
}